// round 14
// baseline (speedup 1.0000x reference)
#include <cuda_runtime.h>
#include <cuda_bf16.h>
#include <math_constants.h>

#define N_ 64
#define T_ 2048
#define D_ 256
#define ETILE 64
#define NTILES (T_ / ETILE)    // 32 tiles per n
#define PTHRESH 1e-7f          // drop V rows below this weight (mass <= 2e-4)
#define CAND_DELTA 16.2f       // ln(1e7): e <= ml_tile - 16.2 => p < 1e-7

// Scratch (no allocs allowed). Only slots of valid tiles (t0 < len) are read
// by the finisher, and those are always written before g_cnt[n] reaches nvt.
__device__ __align__(16) float g_energy[N_ * T_];
__device__ float g_tml[N_ * NTILES];       // per-tile local max
__device__ float g_tsl[N_ * NTILES];       // per-tile sum exp(e - ml)
__device__ int   g_tcc[N_ * NTILES];       // per-tile candidate count
__device__ int   g_candt[N_ * T_];         // candidate t, fixed per-tile slots
__device__ float g_cande[N_ * T_];         // candidate energy
__device__ int   g_cnt[N_];                // completed-tile counters (self-reset)

// Robust lens decode: values in [1, T]. int64 layout => int32 view index 1 == 0.
__device__ __forceinline__ int get_len(const int* __restrict__ lens32, int n) {
    const bool is64 = (lens32[1] == 0);
    return is64 ? lens32[2 * n] : lens32[n];
}

// ---------------------------------------------------------------------------
// Single fused kernel. Grid (NTILES, N) x 256.
// Part 1 (every valid-tile CTA): energy tile + per-tile (ml, sl) + candidates.
// Part 2 (the LAST CTA to finish an n): attn row write + candidate compaction
// + V gather + ctx store for that n. Overlaps finish work with remaining
// energy work; zero extra launches; no global barrier.
// ---------------------------------------------------------------------------
__global__ void __launch_bounds__(256, 3)
k_all(const float* __restrict__ q,
      const float* __restrict__ key,
      const float* __restrict__ val,
      const int* __restrict__ lens32,
      float* __restrict__ attn,
      float* __restrict__ ctx) {
    const int n   = blockIdx.y;
    const int len = get_len(lens32, n);
    const int t0  = blockIdx.x * ETILE;
    if (t0 >= len) return;                    // invalid tile: no work, no count
    const int nvt = (len + ETILE - 1) / ETILE;

    __shared__ float4 qs4[D_ / 4];
    __shared__ float  es[ETILE];
    __shared__ int    s_last;
    const int tid = threadIdx.x;
    if (tid < 64) qs4[tid] = ((const float4*)(q + n * D_))[tid];
    __syncthreads();

    const int warp = tid >> 5, lane = tid & 31;
    const int sub  = lane >> 3;               // row within 4-row group
    const int sl   = lane & 7;                // lane within row (8 lanes/row)

    #pragma unroll
    for (int iter = 0; iter < 2; ++iter) {
        const int r = warp * 8 + iter * 4 + sub;   // row in tile [0,64)
        const int t = t0 + r;
        float s = 0.0f;
        if (t < len) {
            const float4* krow = (const float4*)(key + ((size_t)n * T_ + t) * D_);
            // issue all 8 independent loads first (explicit MLP=8)
            const float4 k0 = krow[sl +  0], k1 = krow[sl +  8];
            const float4 k2 = krow[sl + 16], k3 = krow[sl + 24];
            const float4 k4 = krow[sl + 32], k5 = krow[sl + 40];
            const float4 k6 = krow[sl + 48], k7 = krow[sl + 56];
            const float4 q0 = qs4[sl +  0], q1 = qs4[sl +  8];
            const float4 q2 = qs4[sl + 16], q3 = qs4[sl + 24];
            const float4 q4 = qs4[sl + 32], q5 = qs4[sl + 40];
            const float4 q6 = qs4[sl + 48], q7 = qs4[sl + 56];
            s = k0.x*q0.x + k0.y*q0.y + k0.z*q0.z + k0.w*q0.w
              + k1.x*q1.x + k1.y*q1.y + k1.z*q1.z + k1.w*q1.w
              + k2.x*q2.x + k2.y*q2.y + k2.z*q2.z + k2.w*q2.w
              + k3.x*q3.x + k3.y*q3.y + k3.z*q3.z + k3.w*q3.w
              + k4.x*q4.x + k4.y*q4.y + k4.z*q4.z + k4.w*q4.w
              + k5.x*q5.x + k5.y*q5.y + k5.z*q5.z + k5.w*q5.w
              + k6.x*q6.x + k6.y*q6.y + k6.z*q6.z + k6.w*q6.w
              + k7.x*q7.x + k7.y*q7.y + k7.z*q7.z + k7.w*q7.w;
        }
        s += __shfl_xor_sync(0xffffffff, s, 4);
        s += __shfl_xor_sync(0xffffffff, s, 2);
        s += __shfl_xor_sync(0xffffffff, s, 1);
        if (sl == 0) {
            if (t < len) { g_energy[n * T_ + t] = s; es[r] = s; }
            else         { es[r] = -CUDART_INF_F; }   // never max / candidate
        }
    }
    __syncthreads();

    // CTA epilogue (warp 0): (ml, sl) + ordered candidate push into tile slots
    if (warp == 0) {
        const float v0 = es[lane], v1 = es[lane + 32];
        float ml = fmaxf(v0, v1);
        #pragma unroll
        for (int o = 16; o; o >>= 1)
            ml = fmaxf(ml, __shfl_xor_sync(0xffffffff, ml, o));
        float ssum = __expf(v0 - ml) + __expf(v1 - ml);
        #pragma unroll
        for (int o = 16; o; o >>= 1)
            ssum += __shfl_xor_sync(0xffffffff, ssum, o);

        const float thr = ml - CAND_DELTA;
        const bool l0 = (v0 > thr), l1 = (v1 > thr);   // -inf rows auto-fail
        const unsigned b0 = __ballot_sync(0xffffffff, l0);
        const unsigned b1 = __ballot_sync(0xffffffff, l1);
        const unsigned ltm = (1u << lane) - 1u;
        const int ti   = n * NTILES + blockIdx.x;
        const int base = ti * ETILE;
        if (l0) {
            const int k = __popc(b0 & ltm);
            g_candt[base + k] = t0 + lane;
            g_cande[base + k] = v0;
        }
        const int c0 = __popc(b0);
        if (l1) {
            const int k = c0 + __popc(b1 & ltm);
            g_candt[base + k] = t0 + lane + 32;
            g_cande[base + k] = v1;
        }
        if (lane == 0) {
            g_tml[ti] = ml;
            g_tsl[ti] = ssum;
            g_tcc[ti] = c0 + __popc(b1);
        }
    }

    // ---- completion protocol: every thread fences its global writes, then
    // tid 0 bumps the per-n counter; the last CTA becomes the finisher. ----
    __threadfence();
    __syncthreads();
    if (tid == 0) s_last = (atomicAdd(&g_cnt[n], 1) == nvt - 1) ? 1 : 0;
    __syncthreads();
    if (!s_last) return;
    if (tid == 0) g_cnt[n] = 0;               // self-reset for graph replay

    // =================== finisher: attn + ctx for this n ====================
    __shared__ float  sM, sInvZ;
    __shared__ int    stcc[NTILES];
    __shared__ int    wtot[9];
    __shared__ int    sidx[T_];
    __shared__ float  sp[T_];
    __shared__ float4 red[4][64];

    if (warp == 0) {                          // m, Z from valid tile summaries
        const bool valid = (lane * ETILE) < len;
        const float ml = valid ? g_tml[n * NTILES + lane] : -CUDART_INF_F;
        const float sv = valid ? g_tsl[n * NTILES + lane] : 0.0f;
        float m = ml;
        #pragma unroll
        for (int o = 16; o; o >>= 1)
            m = fmaxf(m, __shfl_xor_sync(0xffffffff, m, o));
        float c = valid ? sv * __expf(ml - m) : 0.0f;
        #pragma unroll
        for (int o = 16; o; o >>= 1) c += __shfl_xor_sync(0xffffffff, c, o);
        if (lane == 0) { sM = m; sInvZ = 1.0f / c; }
    }
    if (warp == 1)                            // candidate counts
        stcc[lane] = ((lane * ETILE) < len) ? g_tcc[n * NTILES + lane] : 0;
    __syncthreads();
    const float m = sM, invZ = sInvZ;

    // ---- attn row: 512 float4, 2 per thread, coalesced ----
    #pragma unroll
    for (int j = tid; j < T_ / 4; j += 256) {
        const int tb = j * 4;
        const float4 e4 = *(const float4*)&g_energy[n * T_ + tb];
        float4 p;
        p.x = (tb + 0 < len) ? __expf(e4.x - m) * invZ : 0.0f;
        p.y = (tb + 1 < len) ? __expf(e4.y - m) * invZ : 0.0f;
        p.z = (tb + 2 < len) ? __expf(e4.z - m) * invZ : 0.0f;
        p.w = (tb + 3 < len) ? __expf(e4.w - m) * invZ : 0.0f;
        *(float4*)&attn[n * T_ + tb] = p;
    }

    // ---- ctx: order-preserving compaction of candidates, V gather ----
    int tk[8]; float pk[8];
    unsigned livem = 0; int cnt = 0;
    #pragma unroll
    for (int k = 0; k < 8; ++k) {
        const int s    = tid * 8 + k;
        const int tile = s >> 6, slot = s & 63;
        bool live = (slot < stcc[tile]);
        float p = 0.0f;
        if (live) {
            const int idx = (n * NTILES + tile) * ETILE + slot;
            p = __expf(g_cande[idx] - m) * invZ;
            tk[k] = g_candt[idx];
            live = (p > PTHRESH);
        }
        pk[k] = p;
        if (live) { livem |= (1u << k); ++cnt; }
    }
    int inc = cnt;
    #pragma unroll
    for (int o = 1; o < 32; o <<= 1) {
        const int v = __shfl_up_sync(0xffffffff, inc, o);
        if (lane >= o) inc += v;
    }
    if (lane == 31) wtot[warp] = inc;
    __syncthreads();
    if (tid == 0) {
        int run = 0;
        #pragma unroll
        for (int w = 0; w < 8; ++w) { const int c = wtot[w]; wtot[w] = run; run += c; }
        wtot[8] = run;
    }
    __syncthreads();
    int off = wtot[warp] + inc - cnt;
    #pragma unroll
    for (int k = 0; k < 8; ++k)
        if ((livem >> k) & 1u) { sidx[off] = tk[k]; sp[off] = pk[k]; ++off; }
    __syncthreads();
    const int sc = wtot[8];                   // >= 1 (max row has p = 1/Z)

    const int d4 = tid & 63;
    const int rg = tid >> 6;
    const float4* v4 = (const float4*)(val + (size_t)n * T_ * D_) + d4;
    float4 acc = make_float4(0.f, 0.f, 0.f, 0.f);
    #pragma unroll 4
    for (int j = rg; j < sc; j += 4) {
        const float  pw = sp[j];
        const float4 v  = v4[(size_t)sidx[j] * 64];
        acc.x += pw * v.x; acc.y += pw * v.y; acc.z += pw * v.z; acc.w += pw * v.w;
    }
    red[rg][d4] = acc;
    __syncthreads();
    if (rg == 0) {
        const float4 a = red[0][d4], b = red[1][d4], c = red[2][d4], e = red[3][d4];
        float4 out;
        out.x = a.x + b.x + c.x + e.x;
        out.y = a.y + b.y + c.y + e.y;
        out.z = a.z + b.z + c.z + e.z;
        out.w = a.w + b.w + c.w + e.w;
        *(float4*)&ctx[n * D_ + d4 * 4] = out;
    }
}

// ---------------------------------------------------------------------------
extern "C" void kernel_launch(void* const* d_in, const int* in_sizes, int n_in,
                              void* d_out, int out_size) {
    const float* q    = (const float*)d_in[0];
    const float* key  = (const float*)d_in[1];
    const float* val  = (const float*)d_in[2];
    const int*   lens = (const int*)d_in[3];
    float* ctx  = (float*)d_out;            // first tuple element: [N, D]
    float* attn = (float*)d_out + N_ * D_;  // second tuple element: [N, T]

    k_all<<<dim3(NTILES, N_), 256>>>(q, key, val, lens, attn, ctx);
}

// round 15
// speedup vs baseline: 1.2557x; 1.2557x over previous
#include <cuda_runtime.h>
#include <cuda_bf16.h>
#include <math_constants.h>

#define N_ 64
#define T_ 2048
#define D_ 256
#define ETILE 64
#define NTILES (T_ / ETILE)    // 32 tiles per n
#define PTHRESH 1e-7f          // drop V rows below this weight (mass <= 2e-4)
#define CAND_DELTA 16.2f       // ln(1e7): e <= ml_tile - 16.2 => p < 1e-7

// Scratch (no allocs allowed). Only slots of valid tiles (t0 < len) are read
// downstream, and those are always written by k_energy on every call.
__device__ __align__(16) float g_energy[N_ * T_];
__device__ float g_tml[N_ * NTILES];       // per-tile local max
__device__ float g_tsl[N_ * NTILES];       // per-tile sum exp(e - ml)
__device__ int   g_tcc[N_ * NTILES];       // per-tile candidate count
__device__ int   g_candt[N_ * T_];         // candidate t, fixed per-tile slots
__device__ float g_cande[N_ * T_];         // candidate energy

// Robust lens decode: values in [1, T]. int64 layout => int32 view index 1 == 0.
__device__ __forceinline__ int get_len(const int* __restrict__ lens32, int n) {
    const bool is64 = (lens32[1] == 0);
    return is64 ? lens32[2 * n] : lens32[n];
}

// ---------------------------------------------------------------------------
// K1: e[n,t] = <key[n,t,:], q[n,:]>; per-tile (ml, sl) + candidate recording.
// Grid (T/64, N) x 256. 8 lanes/row, TWO rows per lane with ALL 16 float4
// loads issued up front (MLP=16, no serialization point between row groups);
// the two shfl-reduction chains run interleaved.
// ---------------------------------------------------------------------------
__global__ void __launch_bounds__(256, 3)
k_energy(const float* __restrict__ q,
         const float* __restrict__ key,
         const int* __restrict__ lens32) {
    const int n   = blockIdx.y;
    const int len = get_len(lens32, n);
    const int t0  = blockIdx.x * ETILE;
    if (t0 >= len) return;                    // invalid tile: never read downstream

    __shared__ float4 qs4[D_ / 4];
    __shared__ float  es[ETILE];
    const int tid = threadIdx.x;
    if (tid < 64) qs4[tid] = ((const float4*)(q + n * D_))[tid];
    __syncthreads();

    const int warp = tid >> 5, lane = tid & 31;
    const int sub  = lane >> 3;               // row within 4-row group
    const int sl   = lane & 7;                // lane within row (8 lanes/row)

    const int r0 = warp * 8 + sub;            // first row in tile [0,32)
    const int r1 = r0 + 4;                    // second row [4,36)... interleaved
    const int tA = t0 + r0;
    const int tB = t0 + r1;
    // rows are always within the T-extent of the array: loads are safe even
    // past len (masked below); only boundary tiles read a little extra.
    const float4* krowA = (const float4*)(key + ((size_t)n * T_ + tA) * D_);
    const float4* krowB = (const float4*)(key + ((size_t)n * T_ + tB) * D_);

    // issue ALL 16 independent loads first (explicit MLP=16)
    const float4 a0 = krowA[sl +  0], a1 = krowA[sl +  8];
    const float4 a2 = krowA[sl + 16], a3 = krowA[sl + 24];
    const float4 a4 = krowA[sl + 32], a5 = krowA[sl + 40];
    const float4 a6 = krowA[sl + 48], a7 = krowA[sl + 56];
    const float4 b0 = krowB[sl +  0], b1 = krowB[sl +  8];
    const float4 b2 = krowB[sl + 16], b3 = krowB[sl + 24];
    const float4 b4 = krowB[sl + 32], b5 = krowB[sl + 40];
    const float4 b6 = krowB[sl + 48], b7 = krowB[sl + 56];

    float s0, s1;
    {
        const float4 q0 = qs4[sl +  0], q1 = qs4[sl +  8];
        const float4 q2 = qs4[sl + 16], q3 = qs4[sl + 24];
        const float4 q4 = qs4[sl + 32], q5 = qs4[sl + 40];
        const float4 q6 = qs4[sl + 48], q7 = qs4[sl + 56];
        s0 = a0.x*q0.x + a0.y*q0.y + a0.z*q0.z + a0.w*q0.w
           + a1.x*q1.x + a1.y*q1.y + a1.z*q1.z + a1.w*q1.w
           + a2.x*q2.x + a2.y*q2.y + a2.z*q2.z + a2.w*q2.w
           + a3.x*q3.x + a3.y*q3.y + a3.z*q3.z + a3.w*q3.w
           + a4.x*q4.x + a4.y*q4.y + a4.z*q4.z + a4.w*q4.w
           + a5.x*q5.x + a5.y*q5.y + a5.z*q5.z + a5.w*q5.w
           + a6.x*q6.x + a6.y*q6.y + a6.z*q6.z + a6.w*q6.w
           + a7.x*q7.x + a7.y*q7.y + a7.z*q7.z + a7.w*q7.w;
        s1 = b0.x*q0.x + b0.y*q0.y + b0.z*q0.z + b0.w*q0.w
           + b1.x*q1.x + b1.y*q1.y + b1.z*q1.z + b1.w*q1.w
           + b2.x*q2.x + b2.y*q2.y + b2.z*q2.z + b2.w*q2.w
           + b3.x*q3.x + b3.y*q3.y + b3.z*q3.z + b3.w*q3.w
           + b4.x*q4.x + b4.y*q4.y + b4.z*q4.z + b4.w*q4.w
           + b5.x*q5.x + b5.y*q5.y + b5.z*q5.z + b5.w*q5.w
           + b6.x*q6.x + b6.y*q6.y + b6.z*q6.z + b6.w*q6.w
           + b7.x*q7.x + b7.y*q7.y + b7.z*q7.z + b7.w*q7.w;
    }
    // interleaved shfl reductions: the two chains overlap latencies
    s0 += __shfl_xor_sync(0xffffffff, s0, 4);
    s1 += __shfl_xor_sync(0xffffffff, s1, 4);
    s0 += __shfl_xor_sync(0xffffffff, s0, 2);
    s1 += __shfl_xor_sync(0xffffffff, s1, 2);
    s0 += __shfl_xor_sync(0xffffffff, s0, 1);
    s1 += __shfl_xor_sync(0xffffffff, s1, 1);

    if (sl == 0) {
        if (tA < len) g_energy[n * T_ + tA] = s0;
        if (tB < len) g_energy[n * T_ + tB] = s1;
        es[r0] = (tA < len) ? s0 : -CUDART_INF_F;
        es[r1] = (tB < len) ? s1 : -CUDART_INF_F;
    }
    __syncthreads();

    // CTA epilogue (warp 0): (ml, sl) + ordered candidate push into tile slots
    if (warp == 0) {
        const float v0 = es[lane], v1 = es[lane + 32];
        float ml = fmaxf(v0, v1);
        #pragma unroll
        for (int o = 16; o; o >>= 1)
            ml = fmaxf(ml, __shfl_xor_sync(0xffffffff, ml, o));
        float ssum = __expf(v0 - ml) + __expf(v1 - ml);
        #pragma unroll
        for (int o = 16; o; o >>= 1)
            ssum += __shfl_xor_sync(0xffffffff, ssum, o);

        const float thr = ml - CAND_DELTA;
        const bool l0 = (v0 > thr), l1 = (v1 > thr);   // -inf rows auto-fail
        const unsigned b0 = __ballot_sync(0xffffffff, l0);
        const unsigned b1 = __ballot_sync(0xffffffff, l1);
        const unsigned ltm = (1u << lane) - 1u;
        const int ti   = n * NTILES + blockIdx.x;
        const int base = ti * ETILE;
        if (l0) {
            const int k = __popc(b0 & ltm);
            g_candt[base + k] = t0 + lane;
            g_cande[base + k] = v0;
        }
        const int c0 = __popc(b0);
        if (l1) {
            const int k = c0 + __popc(b1 & ltm);
            g_candt[base + k] = t0 + lane + 32;
            g_cande[base + k] = v1;
        }
        if (lane == 0) {
            g_tml[ti] = ml;
            g_tsl[ti] = ssum;
            g_tcc[ti] = c0 + __popc(b1);
        }
    }
}

// ---------------------------------------------------------------------------
// K2: finish. Grid (3, N) x 256. Every CTA recomputes (m, Z) from the 32 tile
// summaries. bx<2: float4-streaming attn write. bx==2: order-preserving
// compaction of candidates -> exact p>PTHRESH filter -> V gather -> ctx store.
// ---------------------------------------------------------------------------
__global__ void __launch_bounds__(256, 3)
k_finish(const float* __restrict__ val,
         const int* __restrict__ lens32,
         float* __restrict__ attn,
         float* __restrict__ ctx) {
    const int n   = blockIdx.y;
    const int len = get_len(lens32, n);
    const int tid = threadIdx.x;
    const int warp = tid >> 5, lane = tid & 31;

    __shared__ float sM, sInvZ;
    if (warp == 0) {                          // m, Z from valid tile summaries
        const bool valid = (lane * ETILE) < len;
        const float ml = valid ? g_tml[n * NTILES + lane] : -CUDART_INF_F;
        const float sv = valid ? g_tsl[n * NTILES + lane] : 0.0f;
        float m = ml;
        #pragma unroll
        for (int o = 16; o; o >>= 1)
            m = fmaxf(m, __shfl_xor_sync(0xffffffff, m, o));
        float c = valid ? sv * __expf(ml - m) : 0.0f;
        #pragma unroll
        for (int o = 16; o; o >>= 1) c += __shfl_xor_sync(0xffffffff, c, o);
        if (lane == 0) { sM = m; sInvZ = 1.0f / c; }
    }
    __syncthreads();
    const float m = sM, invZ = sInvZ;

    if (blockIdx.x < 2) {                     // -------- attn streaming --------
        const int t0 = blockIdx.x * 1024 + tid * 4;
        const float4 e4 = *(const float4*)&g_energy[n * T_ + t0];
        float4 p;
        p.x = (t0 + 0 < len) ? __expf(e4.x - m) * invZ : 0.0f;
        p.y = (t0 + 1 < len) ? __expf(e4.y - m) * invZ : 0.0f;
        p.z = (t0 + 2 < len) ? __expf(e4.z - m) * invZ : 0.0f;
        p.w = (t0 + 3 < len) ? __expf(e4.w - m) * invZ : 0.0f;
        *(float4*)&attn[n * T_ + t0] = p;
        return;
    }

    // ------------------------------- ctx -----------------------------------
    __shared__ int    stcc[NTILES];
    __shared__ int    wtot[9];
    __shared__ int    sidx[T_];
    __shared__ float  sp[T_];
    __shared__ float4 red[4][64];

    if (tid < NTILES)
        stcc[tid] = ((tid * ETILE) < len) ? g_tcc[n * NTILES + tid] : 0;
    __syncthreads();

    // each thread owns 8 contiguous candidate slots; order-preserving compact
    int tk[8]; float pk[8];
    unsigned livem = 0; int cnt = 0;
    #pragma unroll
    for (int k = 0; k < 8; ++k) {
        const int s    = tid * 8 + k;
        const int tile = s >> 6, slot = s & 63;
        bool live = (slot < stcc[tile]);
        float p = 0.0f;
        if (live) {
            const int idx = (n * NTILES + tile) * ETILE + slot;
            p = __expf(g_cande[idx] - m) * invZ;
            tk[k] = g_candt[idx];
            live = (p > PTHRESH);
        }
        pk[k] = p;
        if (live) { livem |= (1u << k); ++cnt; }
    }
    int inc = cnt;
    #pragma unroll
    for (int o = 1; o < 32; o <<= 1) {
        const int v = __shfl_up_sync(0xffffffff, inc, o);
        if (lane >= o) inc += v;
    }
    if (lane == 31) wtot[warp] = inc;
    __syncthreads();
    if (tid == 0) {
        int run = 0;
        #pragma unroll
        for (int w = 0; w < 8; ++w) { const int c = wtot[w]; wtot[w] = run; run += c; }
        wtot[8] = run;
    }
    __syncthreads();
    int off = wtot[warp] + inc - cnt;
    #pragma unroll
    for (int k = 0; k < 8; ++k)
        if ((livem >> k) & 1u) { sidx[off] = tk[k]; sp[off] = pk[k]; ++off; }
    __syncthreads();
    const int sc = wtot[8];                   // >= 1 (max row has p = 1/Z)

    // gather surviving V rows: 64 float4 columns x 4 row groups
    const int d4 = tid & 63;
    const int rg = tid >> 6;
    const float4* v4 = (const float4*)(val + (size_t)n * T_ * D_) + d4;
    float4 acc = make_float4(0.f, 0.f, 0.f, 0.f);
    #pragma unroll 4
    for (int j = rg; j < sc; j += 4) {
        const float  pw = sp[j];
        const float4 v  = v4[(size_t)sidx[j] * 64];
        acc.x += pw * v.x; acc.y += pw * v.y; acc.z += pw * v.z; acc.w += pw * v.w;
    }
    red[rg][d4] = acc;
    __syncthreads();
    if (rg == 0) {
        const float4 a = red[0][d4], b = red[1][d4], c = red[2][d4], e = red[3][d4];
        float4 out;
        out.x = a.x + b.x + c.x + e.x;
        out.y = a.y + b.y + c.y + e.y;
        out.z = a.z + b.z + c.z + e.z;
        out.w = a.w + b.w + c.w + e.w;
        *(float4*)&ctx[n * D_ + d4 * 4] = out;   // direct store, no init/atomics
    }
}

// ---------------------------------------------------------------------------
extern "C" void kernel_launch(void* const* d_in, const int* in_sizes, int n_in,
                              void* d_out, int out_size) {
    const float* q    = (const float*)d_in[0];
    const float* key  = (const float*)d_in[1];
    const float* val  = (const float*)d_in[2];
    const int*   lens = (const int*)d_in[3];
    float* ctx  = (float*)d_out;            // first tuple element: [N, D]
    float* attn = (float*)d_out + N_ * D_;  // second tuple element: [N, T]

    k_energy<<<dim3(T_ / ETILE, N_), 256>>>(q, key, lens);
    k_finish<<<dim3(3, N_), 256>>>(val, lens, attn, ctx);
}